// round 8
// baseline (speedup 1.0000x reference)
#include <cuda_runtime.h>
#include <cstdint>
#include <mma.h>
#include <math.h>

using namespace nvcuda;

#define BB 16      // batch
#define NR 512     // real points
#define NP 384     // padding points
#define NT 896     // total points per side
#define DD 256     // feature dim

// ---------------- scratch ----------------
__device__ float d_f1n[BB*NT*DD];       // normalized f1 (tf32-rounded)
__device__ float d_f2n[BB*NT*DD];       // normalized f2 (tf32-rounded)
__device__ float d_x3r[BB*NP*DD];       // tf32-rounded raw x3
__device__ float d_x4r[BB*NP*DD];       // tf32-rounded raw x4
__device__ float d_S  [BB*NR*NR];       // S then C (in-place)
__device__ float d_CT [BB*NR*NR];       // C transposed
__device__ float d_srp[BB*7*NT];
__device__ float d_scp[BB*7*NT];
__device__ float d_sr[BB*NT];
__device__ float d_sc[BB*NT];
__device__ float d_fb[2][BB*NR];        // f dual ping-pong
__device__ float d_gb[2][BB*NR];        // g dual ping-pong
__device__ float d_ff[BB*NR];           // final f
__device__ float d_gf[BB*NR];           // final g
__device__ float d_hpart[144];

// grid-barrier state (g_cnt returns to 0 after every barrier; g_gen monotonic)
__device__ unsigned int g_cnt;
__device__ unsigned int g_gen;

// ---------------- FMA-only helpers ----------------
__device__ __forceinline__ float fexp(float x) {
    x = fmaxf(x, -87.0f);
    const float L2E_HI = 1.4426950216293335f;
    const float L2E_LO = 1.9259630e-8f;
    float y = fmaf(x, L2E_HI, 12582912.0f);
    int   n = __float_as_int(y) - 0x4B400000;
    float fi = y - 12582912.0f;
    float r = fmaf(x, L2E_HI, -fi);
    r = fmaf(x, L2E_LO, r);
    float t = r * 0.69314718055994531f;
    float p = 1.3888889e-3f;
    p = fmaf(p, t, 8.3333333e-3f);
    p = fmaf(p, t, 4.1666667e-2f);
    p = fmaf(p, t, 1.6666667e-1f);
    p = fmaf(p, t, 0.5f);
    p = fmaf(p, t, 1.0f);
    p = fmaf(p, t, 1.0f);
    return p * __int_as_float((n + 127) << 23);
}

__device__ __forceinline__ float frcp(float x) {
    float r = __int_as_float(0x7EF311C3 - __float_as_int(x));
    r = r * fmaf(-x, r, 2.0f);
    r = r * fmaf(-x, r, 2.0f);
    r = r * fmaf(-x, r, 2.0f);
    return r;
}

__device__ __forceinline__ void cp16(void* s, const void* g) {
    unsigned int sa = (unsigned int)__cvta_generic_to_shared(s);
    asm volatile("cp.async.cg.shared.global [%0], [%1], 16;" :: "r"(sa), "l"(g));
}

__device__ __forceinline__ float4 tf32x4(float4 v) {
    v.x = wmma::__float_to_tf32(v.x);
    v.y = wmma::__float_to_tf32(v.y);
    v.z = wmma::__float_to_tf32(v.z);
    v.w = wmma::__float_to_tf32(v.w);
    return v;
}

// software grid barrier (fence + relaxed atomics)
__device__ __forceinline__ void gridsync(int nb) {
    __threadfence();
    __syncthreads();
    if (threadIdx.x == 0) {
        unsigned int gen = atomicAdd(&g_gen, 0u);
        if (atomicAdd(&g_cnt, 1u) == (unsigned int)(nb - 1)) {
            atomicExch(&g_cnt, 0u);
            __threadfence();
            atomicAdd(&g_gen, 1u);
        } else {
            while (atomicAdd(&g_gen, 0u) == gen) { __nanosleep(64); }
        }
        __threadfence();
    }
    __syncthreads();
}

// ---------------- 1) normalize + tf32-round; also emit rounded raw x3/x4 ----------------
__global__ void __launch_bounds__(256) k_normalize(
    const float* __restrict__ x1, const float* __restrict__ x2,
    const float* __restrict__ x3, const float* __restrict__ x4)
{
    int gw   = blockIdx.x * 8 + (threadIdx.x >> 5);
    int lane = threadIdx.x & 31;
    int which = (gw >= BB*NT) ? 1 : 0;
    int r     = which ? gw - BB*NT : gw;
    int b = r / NT, i = r % NT;
    const float* src;
    float* rawdst = nullptr;
    if (i < NR) {
        src = (which ? x2 : x1) + ((size_t)(b*NR + i)) * DD;
    } else {
        size_t off = ((size_t)(b*NP + (i - NR))) * DD;
        src = (which ? x4 : x3) + off;
        rawdst = (which ? d_x4r : d_x3r) + off;
    }
    float* dst = (which ? d_f2n : d_f1n) + (size_t)r * DD;

    float4 v0 = *(const float4*)(src + lane*4);
    float4 v1 = *(const float4*)(src + 128 + lane*4);
    if (rawdst) {
        *(float4*)(rawdst + lane*4)       = tf32x4(v0);
        *(float4*)(rawdst + 128 + lane*4) = tf32x4(v1);
    }
    float sq = v0.x*v0.x + v0.y*v0.y + v0.z*v0.z + v0.w*v0.w
             + v1.x*v1.x + v1.y*v1.y + v1.z*v1.z + v1.w*v1.w;
    #pragma unroll
    for (int o = 16; o; o >>= 1) sq += __shfl_xor_sync(0xffffffffu, sq, o);
    float rn = 1.0f / fmaxf(sqrtf(sq), 1e-12f);
    v0.x *= rn; v0.y *= rn; v0.z *= rn; v0.w *= rn;
    v1.x *= rn; v1.y *= rn; v1.z *= rn; v1.w *= rn;
    *(float4*)(dst + lane*4)       = tf32x4(v0);
    *(float4*)(dst + 128 + lane*4) = tf32x4(v1);
}

// ---------------- 2) pipelined tf32 GEMM, 4 warps x (64x64) ----------------
#define LDA 36                // ≡4 mod 32 -> conflict-free fragment loads
#define LDE 132
#define STAGE (128*LDA)       // 4608 floats
#define SIM_SMEM (4*STAGE*4)  // 73728 bytes (>= 128*LDE*4 = 67584 for epilogue)

__global__ void __launch_bounds__(128) k_simgemm()
{
    extern __shared__ float sh[];

    int b  = blockIdx.z;
    int m0 = blockIdx.y * 128, n0 = blockIdx.x * 128;
    if (m0 >= NR && n0 >= NR) return;   // padding x padding feeds nothing

    const float* Ag = d_f1n + (size_t)b * NT * DD + (size_t)m0 * DD;
    const float* Bg = d_f2n + (size_t)b * NT * DD + (size_t)n0 * DD;

    int tid = threadIdx.x;              // 128 threads, 4 warps
    int wid = tid >> 5;
    int warp_m = wid >> 1;              // 0..1
    int warp_n = wid & 1;               // 0..1

    wmma::fragment<wmma::accumulator,16,16,8,float> acc[4][4];
    #pragma unroll
    for (int mt = 0; mt < 4; mt++)
        #pragma unroll
        for (int nt = 0; nt < 4; nt++)
            wmma::fill_fragment(acc[mt][nt], 0.0f);

    int lrow = tid >> 3;                // 0..15
    int lc4  = (tid & 7) * 4;

    {
        float* A = sh; float* B = sh + STAGE;
        #pragma unroll
        for (int u = 0; u < 8; u++) {
            int row = lrow + 16*u;
            cp16(&A[row*LDA + lc4], Ag + (size_t)row*DD + lc4);
            cp16(&B[row*LDA + lc4], Bg + (size_t)row*DD + lc4);
        }
        asm volatile("cp.async.commit_group;");
    }

    for (int kc = 0; kc < 8; kc++) {
        if (kc < 7) {
            float* A = sh + ((kc+1)&1)*2*STAGE;
            float* B = A + STAGE;
            int k0 = (kc+1)*32;
            #pragma unroll
            for (int u = 0; u < 8; u++) {
                int row = lrow + 16*u;
                cp16(&A[row*LDA + lc4], Ag + (size_t)row*DD + k0 + lc4);
                cp16(&B[row*LDA + lc4], Bg + (size_t)row*DD + k0 + lc4);
            }
            asm volatile("cp.async.commit_group;");
            asm volatile("cp.async.wait_group 1;");
        } else {
            asm volatile("cp.async.wait_group 0;");
        }
        __syncthreads();
        const float* A = sh + (kc&1)*2*STAGE;
        const float* B = A + STAGE;
        #pragma unroll
        for (int ks = 0; ks < 4; ks++) {
            wmma::fragment<wmma::matrix_a,16,16,8,wmma::precision::tf32,wmma::row_major> af[4];
            wmma::fragment<wmma::matrix_b,16,16,8,wmma::precision::tf32,wmma::col_major> bf[4];
            #pragma unroll
            for (int mt = 0; mt < 4; mt++)
                wmma::load_matrix_sync(af[mt], &A[(warp_m*64 + mt*16)*LDA + ks*8], LDA);
            #pragma unroll
            for (int nt = 0; nt < 4; nt++)
                wmma::load_matrix_sync(bf[nt], &B[(warp_n*64 + nt*16)*LDA + ks*8], LDA);
            #pragma unroll
            for (int mt = 0; mt < 4; mt++)
                #pragma unroll
                for (int nt = 0; nt < 4; nt++)
                    wmma::mma_sync(acc[mt][nt], af[mt], bf[nt], acc[mt][nt]);
        }
        __syncthreads();
    }

    // epilogue: store all acc to sh[128][LDE], then thread-per-row fexp + sums
    #pragma unroll
    for (int mt = 0; mt < 4; mt++)
        #pragma unroll
        for (int nt = 0; nt < 4; nt++)
            wmma::store_matrix_sync(&sh[(warp_m*64 + mt*16)*LDE + warp_n*64 + nt*16],
                                    acc[mt][nt], LDE, wmma::mem_row_major);
    __syncthreads();

    bool inblk = (m0 < NR) && (n0 < NR);
    int ig = m0 + tid;
    float rsum = 0.f;
    float* Srow = d_S + ((size_t)b*NR + ig)*NR + n0;
    #pragma unroll
    for (int q = 0; q < 32; q++) {
        float4 v4 = *(float4*)&sh[tid*LDE + q*4];
        v4.x = fexp(10.0f * v4.x);
        v4.y = fexp(10.0f * v4.y);
        v4.z = fexp(10.0f * v4.z);
        v4.w = fexp(10.0f * v4.w);
        rsum += (v4.x + v4.y) + (v4.z + v4.w);
        *(float4*)&sh[tid*LDE + q*4] = v4;
        if (inblk) *(float4*)(Srow + q*4) = v4;
    }
    d_srp[((size_t)b*7 + (n0 >> 7))*NT + ig] = rsum;
    __syncthreads();

    float cs = 0.f;
    #pragma unroll 8
    for (int r = 0; r < 128; r++) cs += sh[r*LDE + tid];
    d_scp[((size_t)b*7 + (m0 >> 7))*NT + n0 + tid] = cs;
}

// ---------------- 3) hinge GEMM (pipelined tf32, 8 warps x (64x32)) ----------------
__global__ void __launch_bounds__(256) k_hinge()
{
    extern __shared__ float sh[];
    int b  = blockIdx.z;
    int m0 = blockIdx.y * 128, n0 = blockIdx.x * 128;
    const float* Ag = d_x3r + (size_t)b * NP * DD + (size_t)m0 * DD;
    const float* Bg = d_x4r + (size_t)b * NP * DD + (size_t)n0 * DD;

    int tid = threadIdx.x;
    int wid = tid >> 5;
    int warp_m = wid >> 2;
    int warp_n = wid & 3;

    wmma::fragment<wmma::accumulator,16,16,8,float> acc[4][2];
    #pragma unroll
    for (int mt = 0; mt < 4; mt++)
        #pragma unroll
        for (int nt = 0; nt < 2; nt++)
            wmma::fill_fragment(acc[mt][nt], 0.0f);

    int lrow = tid >> 3;
    int lc4  = (tid & 7) * 4;

    {
        float* A = sh; float* B = sh + STAGE;
        #pragma unroll
        for (int u = 0; u < 4; u++) {
            int row = lrow + 32*u;
            cp16(&A[row*LDA + lc4], Ag + (size_t)row*DD + lc4);
            cp16(&B[row*LDA + lc4], Bg + (size_t)row*DD + lc4);
        }
        asm volatile("cp.async.commit_group;");
    }

    for (int kc = 0; kc < 8; kc++) {
        if (kc < 7) {
            float* A = sh + ((kc+1)&1)*2*STAGE;
            float* B = A + STAGE;
            int k0 = (kc+1)*32;
            #pragma unroll
            for (int u = 0; u < 4; u++) {
                int row = lrow + 32*u;
                cp16(&A[row*LDA + lc4], Ag + (size_t)row*DD + k0 + lc4);
                cp16(&B[row*LDA + lc4], Bg + (size_t)row*DD + k0 + lc4);
            }
            asm volatile("cp.async.commit_group;");
            asm volatile("cp.async.wait_group 1;");
        } else {
            asm volatile("cp.async.wait_group 0;");
        }
        __syncthreads();
        const float* A = sh + (kc&1)*2*STAGE;
        const float* B = A + STAGE;
        #pragma unroll
        for (int ks = 0; ks < 4; ks++) {
            wmma::fragment<wmma::matrix_b,16,16,8,wmma::precision::tf32,wmma::col_major> bf[2];
            #pragma unroll
            for (int nt = 0; nt < 2; nt++)
                wmma::load_matrix_sync(bf[nt], &B[(warp_n*32 + nt*16)*LDA + ks*8], LDA);
            #pragma unroll
            for (int mt = 0; mt < 4; mt++) {
                wmma::fragment<wmma::matrix_a,16,16,8,wmma::precision::tf32,wmma::row_major> af;
                wmma::load_matrix_sync(af, &A[(warp_m*64 + mt*16)*LDA + ks*8], LDA);
                #pragma unroll
                for (int nt = 0; nt < 2; nt++)
                    wmma::mma_sync(acc[mt][nt], af, bf[nt], acc[mt][nt]);
            }
        }
        __syncthreads();
    }

    float loc = 0.f;
    #pragma unroll
    for (int mt = 0; mt < 4; mt++)
        #pragma unroll
        for (int nt = 0; nt < 2; nt++)
            #pragma unroll
            for (int e = 0; e < acc[mt][nt].num_elements; e++)
                loc += fmaxf(0.1f - acc[mt][nt].x[e], 0.0f);

    __shared__ float red[8];
    #pragma unroll
    for (int o = 16; o; o >>= 1) loc += __shfl_xor_sync(0xffffffffu, loc, o);
    if ((tid & 31) == 0) red[tid >> 5] = loc;
    __syncthreads();
    if (tid == 0) {
        float tot = 0.f;
        #pragma unroll
        for (int w = 0; w < 8; w++) tot += red[w];
        d_hpart[blockIdx.z * 9 + blockIdx.y * 3 + blockIdx.x] = tot;
    }
}

// ---------------- 4) persistent: sums -> cost/CT -> 10x softmin -> finalize ----------------
#define PGRID 512

__global__ void __launch_bounds__(256, 4) k_persist(float* __restrict__ out)
{
    __shared__ float tile[32][33];
    __shared__ double sa[256];
    __shared__ double sb[256];

    int tid  = threadIdx.x;
    int nb   = gridDim.x;
    int lane = tid & 31;

    // ---- phase A: reduce row/col partial sums (real rows/cols only) ----
    for (int idx = blockIdx.x*256 + tid; idx < 2*BB*NR; idx += nb*256) {
        int which = idx >= BB*NR;
        int r = which ? idx - BB*NR : idx;
        int b = r >> 9, i = r & 511;
        const float* P = (which ? d_scp : d_srp) + (size_t)b*7*NT + i;
        float s = 0.f;
        #pragma unroll
        for (int t = 0; t < 7; t++) s += P[(size_t)t*NT];
        (which ? d_sc : d_sr)[b*NT + i] = s;
    }
    gridsync(nb);

    // ---- phase B: cost C = 1 - s/(sc+sr-s) in-place + C^T ----
    {
        int tx = tid & 31, ty = tid >> 5;   // (32, 8)
        for (int tt = blockIdx.x; tt < BB*256; tt += nb) {
            int b = tt >> 8, rem = tt & 255;
            int i0 = (rem >> 4) << 5, j0 = (rem & 15) << 5;
            float* S  = d_S  + (size_t)b * NR * NR;
            float* CT = d_CT + (size_t)b * NR * NR;
            int j = j0 + tx;
            float scv = d_sc[b * NT + j];
            #pragma unroll
            for (int r = 0; r < 4; r++) {
                int i = i0 + ty + 8*r;
                float s   = S[(size_t)i * NR + j];
                float den = scv + d_sr[b * NT + i] - s;
                float c   = fmaf(-s, frcp(den), 1.0f);
                S[(size_t)i * NR + j] = c;
                tile[ty + 8*r][tx] = c;
            }
            __syncthreads();
            #pragma unroll
            for (int r = 0; r < 4; r++)
                CT[(size_t)(j0 + ty + 8*r) * NR + i0 + tx] = tile[tx][ty + 8*r];
            __syncthreads();
        }
    }
    gridsync(nb);

    // ---- phase C: 10 softmin passes (init, 8 averaged, final extrapolation) ----
    const float EPSA[8] = {9.0f, 9.0f, 2.25f, 0.5625f, 0.140625f,
                           0.03515625f, 0.0087890625f, 0.0025f};
    int gwarp = blockIdx.x*8 + (tid >> 5);
    int cur = 0;
    for (int p = 0; p < 10; p++) {
        float eps, inv_eps;
        const float *hf, *hg, *of, *og;
        float *wf, *wg;
        int avg;
        if (p == 0) {
            eps = 9.0f; inv_eps = 1.0f/9.0f;
            hf = hg = of = og = nullptr;
            wf = d_fb[0]; wg = d_gb[0]; avg = 0;
        } else if (p < 9) {
            eps = EPSA[p-1]; inv_eps = 1.0f/eps;
            hf = d_gb[cur]; hg = d_fb[cur];
            of = d_fb[cur]; og = d_gb[cur];
            wf = d_fb[cur^1]; wg = d_gb[cur^1]; avg = 1;
        } else {
            eps = 0.0025f; inv_eps = 400.0f;
            hf = d_gb[cur]; hg = d_fb[cur];
            of = og = nullptr;
            wf = d_ff; wg = d_gf; avg = 0;
        }

        for (int rw = gwarp; rw < 2*BB*NR; rw += nb*8) {
            int side = rw >= BB*NR;
            int row  = side ? rw - BB*NR : rw;
            int b    = row >> 9;
            const float* Crow = (side ? d_CT : d_S) + (size_t)row * NR;
            const float* hv = side ? hg : hf;
            const float* hb = hv ? hv + (b << 9) : nullptr;

            float a[16];
            #pragma unroll
            for (int q = 0; q < 4; q++) {
                int j = q*128 + lane*4;
                float4 c4 = *(const float4*)(Crow + j);
                if (hb) {
                    float4 h4 = *(const float4*)(hb + j);
                    a[q*4+0] = (h4.x - c4.x) * inv_eps;
                    a[q*4+1] = (h4.y - c4.y) * inv_eps;
                    a[q*4+2] = (h4.z - c4.z) * inv_eps;
                    a[q*4+3] = (h4.w - c4.w) * inv_eps;
                } else {
                    a[q*4+0] = -c4.x * inv_eps;
                    a[q*4+1] = -c4.y * inv_eps;
                    a[q*4+2] = -c4.z * inv_eps;
                    a[q*4+3] = -c4.w * inv_eps;
                }
            }
            float m = a[0];
            #pragma unroll
            for (int u = 1; u < 16; u++) m = fmaxf(m, a[u]);
            #pragma unroll
            for (int o = 16; o; o >>= 1) m = fmaxf(m, __shfl_xor_sync(0xffffffffu, m, o));
            float s = 0.f;
            #pragma unroll
            for (int u = 0; u < 16; u++) s += fexp(a[u] - m);
            #pragma unroll
            for (int o = 16; o; o >>= 1) s += __shfl_xor_sync(0xffffffffu, s, o);
            if (lane == 0) {
                float val = -eps * (m + logf(s));
                if (avg) val = 0.5f * ((side ? og : of)[row] + val);
                (side ? wg : wf)[row] = val;
            }
        }
        if (p > 0 && p < 9) cur ^= 1;
        gridsync(nb);
    }

    // ---- phase D: deterministic finalize (block 0 only) ----
    if (blockIdx.x == 0) {
        double acc = 0.0;
        for (int idx = tid; idx < BB*NR; idx += 256)
            acc += (double)d_ff[idx] + (double)d_gf[idx];
        double h = 0.0;
        for (int idx = tid; idx < 144; idx += 256) h += (double)d_hpart[idx];
        sa[tid] = acc; sb[tid] = h;
        __syncthreads();
        for (int o = 128; o; o >>= 1) {
            if (tid < o) { sa[tid] += sa[tid + o]; sb[tid] += sb[tid + o]; }
            __syncthreads();
        }
        if (tid == 0) {
            out[0] = (float)sb[0];
            out[1] = (float)(sa[0] / (double)BB);
        }
    }
}

// ---------------- host ----------------
extern "C" void kernel_launch(void* const* d_in, const int* in_sizes, int n_in,
                              void* d_out, int out_size)
{
    const float* x1 = (const float*)d_in[0];
    const float* x2 = (const float*)d_in[1];
    const float* x3 = (const float*)d_in[2];
    const float* x4 = (const float*)d_in[3];
    float* out = (float*)d_out;

    cudaFuncSetAttribute(k_simgemm, cudaFuncAttributeMaxDynamicSharedMemorySize, SIM_SMEM);
    cudaFuncSetAttribute(k_hinge,   cudaFuncAttributeMaxDynamicSharedMemorySize, SIM_SMEM);

    k_normalize<<<2*BB*NT/8, 256>>>(x1, x2, x3, x4);
    k_simgemm<<<dim3(7, 7, BB), 128, SIM_SMEM>>>();
    k_hinge<<<dim3(3, 3, BB), 256, SIM_SMEM>>>();
    k_persist<<<PGRID, 256>>>(out);
}